// round 7
// baseline (speedup 1.0000x reference)
#include <cuda_runtime.h>
#include <cuda_fp16.h>
#include <cstdint>
#include <cstddef>

// ---------------------------------------------------------------------------
// softmax(QK^T/32)V with Q/K/V = x W^T + b.
// fp16 mma.sync m16n8k16 (fp32 accum). All GEMMs NT (A[M,K]*B[N,K]^T);
// V produced transposed (Vt = Wv x^T + bv).
// R7: 256-thread CTAs, tile 128x256, 3-stage cp.async, 1 sync per K-chunk.
// ---------------------------------------------------------------------------

#define BT_TOK   16384
#define DMODEL   1024
#define TSEQ     2048
#define NBATCH   8
#define SCALE    0.03125f

// Scratch (device globals; allocation forbidden)
__device__ __half g_qh[(size_t)BT_TOK * DMODEL];          // 32 MB
__device__ __half g_kh[(size_t)BT_TOK * DMODEL];          // 32 MB
__device__ __half g_vth[(size_t)DMODEL * BT_TOK];         // 32 MB  Vt[f, tok]
__device__ float  g_s[(size_t)NBATCH * TSEQ * TSEQ];      // 128 MB scores fp32
__device__ __half g_p[(size_t)NBATCH * TSEQ * TSEQ];      // 64 MB  probs half
__device__ __half g_xh[(size_t)BT_TOK * DMODEL];          // 32 MB
__device__ __half g_wh[3][(size_t)DMODEL * DMODEL];       // 6 MB

// ---------------- helpers ----------------
__device__ __forceinline__ unsigned smem_u32(const void* p) {
    unsigned a;
    asm("{ .reg .u64 t; cvta.to.shared.u64 t, %1; cvt.u32.u64 %0, t; }" : "=r"(a) : "l"(p));
    return a;
}
__device__ __forceinline__ void cp16(unsigned saddr, const void* g) {
    asm volatile("cp.async.cg.shared.global [%0], [%1], 16;" :: "r"(saddr), "l"(g));
}
__device__ __forceinline__ void cp_commit() { asm volatile("cp.async.commit_group;"); }
template <int N> __device__ __forceinline__ void cp_wait() {
    asm volatile("cp.async.wait_group %0;" :: "n"(N));
}
__device__ __forceinline__ void ldsm_x4(uint32_t r[4], unsigned addr) {
    asm volatile("ldmatrix.sync.aligned.m8n8.x4.shared.b16 {%0,%1,%2,%3}, [%4];"
                 : "=r"(r[0]), "=r"(r[1]), "=r"(r[2]), "=r"(r[3]) : "r"(addr));
}
__device__ __forceinline__ void mma_fp16(float c[4], const uint32_t a[4],
                                         uint32_t b0, uint32_t b1) {
    asm volatile(
        "mma.sync.aligned.m16n8k16.row.col.f32.f16.f16.f32 "
        "{%0,%1,%2,%3}, {%4,%5,%6,%7}, {%8,%9}, {%0,%1,%2,%3};"
        : "+f"(c[0]), "+f"(c[1]), "+f"(c[2]), "+f"(c[3])
        : "r"(a[0]), "r"(a[1]), "r"(a[2]), "r"(a[3]), "r"(b0), "r"(b1));
}

// ---------------------------------------------------------------------------
// NT fp16 GEMM: C[M,N] = alpha * A[M,K] * B[N,K]^T (+ bias)
// CTA tile 128(M) x 256(N), 256 threads: warp grid 2(M) x 4(N), warp 64x64.
// K-chunk 32, 3-stage cp.async pipeline, one __syncthreads per chunk.
// Smem rows padded to 40 halves (80 B) -> ldmatrix conflict-free.
// bias_mode: 0 none, 1 per-col, 2 per-row.  out_half: C dtype.
// ---------------------------------------------------------------------------
#define ROWB   80                          // bytes per smem row (40 halves)
#define A_ST   (128 * ROWB)                // 10240 B
#define B_ST   (256 * ROWB)                // 20480 B
#define STG    (A_ST + B_ST)               // 30720 B per stage
#define NSTAGE 3
#define SMEM_G (NSTAGE * STG)              // 92160 B

__global__ void __launch_bounds__(256, 1)
gemm_fp16(const __half* __restrict__ A, int lda, size_t sA,
          const __half* __restrict__ B, int ldb, size_t sB,
          void* __restrict__ Cv, int ldc, size_t sC,
          const float* __restrict__ bias, int bias_mode,
          float alpha, int K, int out_half)
{
    extern __shared__ __align__(128) char smem[];
    const unsigned sb = smem_u32(smem);

    const int tid  = threadIdx.x;
    const int lane = tid & 31;
    const int wid  = tid >> 5;
    const int wm   = (wid & 1) * 64;        // 2 m-positions
    const int wn   = (wid >> 1) * 64;       // 4 n-positions

    A += blockIdx.z * sA;
    B += blockIdx.z * sB;
    const int m0 = blockIdx.y * 128;
    const int n0 = blockIdx.x * 256;

    // ldmatrix per-lane offset (identical mapping to the validated R6 kernel)
    const int li = lane >> 3, lr = lane & 7;
    const unsigned offL = (unsigned)((((li & 1) * 8 + lr) * 40 + (li >> 1) * 8) * 2);

    // staging: rows of 32 halves = 4 x 16B; 256 threads
    const int srow = tid >> 2, scol = (tid & 3) * 8;   // srow 0..63, scol halves

    float acc[4][8][4] = {};

    auto load_stage = [&](int st, int k0) {
        const __half* Ag = A + (size_t)m0 * lda + k0 + scol;
        const unsigned da = sb + st * STG + scol * 2;
#pragma unroll
        for (int p = 0; p < 2; p++)                      // A: 128 rows
            cp16(da + (srow + p * 64) * ROWB, Ag + (size_t)(srow + p * 64) * lda);
        const __half* Bg = B + (size_t)n0 * ldb + k0 + scol;
        const unsigned db = sb + st * STG + A_ST + scol * 2;
#pragma unroll
        for (int p = 0; p < 4; p++)                      // B: 256 rows
            cp16(db + (srow + p * 64) * ROWB, Bg + (size_t)(srow + p * 64) * ldb);
        cp_commit();
    };

    const int NK = K >> 5;                  // >= 32 for this problem
    load_stage(0, 0);
    load_stage(1, 32);

    for (int i = 0; i < NK; i++) {
        const int st = i % NSTAGE;
        if (i + 1 < NK) cp_wait<1>(); else cp_wait<0>();
        __syncthreads();                    // stage i ready; all warps done with i-1
        if (i + 2 < NK) load_stage((i + 2) % NSTAGE, (i + 2) * 32);

        const unsigned Ab = sb + st * STG + offL;
        const unsigned Bb = sb + st * STG + A_ST + offL;

#pragma unroll
        for (int ks = 0; ks < 2; ks++) {
            uint32_t a[4][4];
#pragma unroll
            for (int mt = 0; mt < 4; mt++)
                ldsm_x4(a[mt], Ab + (wm + mt * 16) * ROWB + ks * 32);
            uint32_t bq[4][4];
#pragma unroll
            for (int g = 0; g < 4; g++)
                ldsm_x4(bq[g], Bb + (wn + g * 16) * ROWB + ks * 32);
#pragma unroll
            for (int mt = 0; mt < 4; mt++)
#pragma unroll
                for (int nt = 0; nt < 8; nt++) {
                    const int g = nt >> 1;
                    const uint32_t b0 = (nt & 1) ? bq[g][1] : bq[g][0];
                    const uint32_t b1 = (nt & 1) ? bq[g][3] : bq[g][2];
                    mma_fp16(acc[mt][nt], a[mt], b0, b1);
                }
        }
    }

    // ---- epilogue (rows lane>>2 / +8, cols (lane&3)*2, +1) ----
    float* Cf = (float*)Cv + blockIdx.z * sC;
    __half* Ch = (__half*)Cv + blockIdx.z * sC;

#pragma unroll
    for (int nt = 0; nt < 8; nt++) {
        const int c = n0 + wn + nt * 8 + (lane & 3) * 2;
        float bx = 0.f, by = 0.f;
        if (bias_mode == 1) { bx = bias[c]; by = bias[c + 1]; }
#pragma unroll
        for (int mt = 0; mt < 4; mt++) {
            const int r = m0 + wm + mt * 16 + (lane >> 2);
            float r0x = acc[mt][nt][0] * alpha, r0y = acc[mt][nt][1] * alpha;
            float r1x = acc[mt][nt][2] * alpha, r1y = acc[mt][nt][3] * alpha;
            if (bias_mode == 1) { r0x += bx; r0y += by; r1x += bx; r1y += by; }
            else if (bias_mode == 2) {
                const float b0 = bias[r], b1 = bias[r + 8];
                r0x += b0; r0y += b0; r1x += b1; r1y += b1;
            }
            if (out_half) {
                *(__half2*)(Ch + (size_t)r * ldc + c)       = __floats2half2_rn(r0x, r0y);
                *(__half2*)(Ch + (size_t)(r + 8) * ldc + c) = __floats2half2_rn(r1x, r1y);
            } else {
                *(float2*)(Cf + (size_t)r * ldc + c)       = make_float2(r0x, r0y);
                *(float2*)(Cf + (size_t)(r + 8) * ldc + c) = make_float2(r1x, r1y);
            }
        }
    }
}

// ---------------------------------------------------------------------------
// fp32 -> fp16 conversion (rn).
// ---------------------------------------------------------------------------
__global__ void __launch_bounds__(256)
f2h_kernel(const float4* __restrict__ in, __half2* __restrict__ out, int n4)
{
    int i = blockIdx.x * blockDim.x + threadIdx.x;
    if (i < n4) {
        float4 v = in[i];
        out[2 * i]     = __floats2half2_rn(v.x, v.y);
        out[2 * i + 1] = __floats2half2_rn(v.z, v.w);
    }
}

// ---------------------------------------------------------------------------
// Row softmax over 2048-wide fp32 rows -> fp16 probabilities.
// ---------------------------------------------------------------------------
__global__ void __launch_bounds__(256)
softmax2048(const float* __restrict__ S, __half* __restrict__ P)
{
    const int row = blockIdx.x;
    const float* p = S + (size_t)row * 2048;
    __half* o = P + (size_t)row * 2048;
    const int t = threadIdx.x;

    float v[8];
#pragma unroll
    for (int i = 0; i < 8; i++) v[i] = p[t + i * 256];

    float m = v[0];
#pragma unroll
    for (int i = 1; i < 8; i++) m = fmaxf(m, v[i]);
#pragma unroll
    for (int o2 = 16; o2; o2 >>= 1) m = fmaxf(m, __shfl_xor_sync(0xffffffffu, m, o2));

    __shared__ float red[8];
    if ((t & 31) == 0) red[t >> 5] = m;
    __syncthreads();
#pragma unroll
    for (int i = 0; i < 8; i++) m = fmaxf(m, red[i]);

    float s = 0.0f;
#pragma unroll
    for (int i = 0; i < 8; i++) { v[i] = __expf(v[i] - m); s += v[i]; }
#pragma unroll
    for (int o2 = 16; o2; o2 >>= 1) s += __shfl_xor_sync(0xffffffffu, s, o2);

    __syncthreads();
    if ((t & 31) == 0) red[t >> 5] = s;
    __syncthreads();
    s = 0.0f;
#pragma unroll
    for (int i = 0; i < 8; i++) s += red[i];

    const float inv = 1.0f / s;
#pragma unroll
    for (int i = 0; i < 8; i++) o[t + i * 256] = __float2half_rn(v[i] * inv);
}

// ---------------------------------------------------------------------------
// Launch pipeline (graph-capturable: kernels only)
// ---------------------------------------------------------------------------
extern "C" void kernel_launch(void* const* d_in, const int* in_sizes, int n_in,
                              void* d_out, int out_size)
{
    (void)in_sizes; (void)n_in; (void)out_size;
    const float* x  = (const float*)d_in[0];
    const float* Wq = (const float*)d_in[1];
    const float* bq = (const float*)d_in[2];
    const float* Wk = (const float*)d_in[3];
    const float* bk = (const float*)d_in[4];
    const float* Wv = (const float*)d_in[5];
    const float* bv = (const float*)d_in[6];
    float* out = (float*)d_out;

    __half *qh, *kh, *vth, *ph, *xh, *wh;
    float* s;
    cudaGetSymbolAddress((void**)&qh,  g_qh);
    cudaGetSymbolAddress((void**)&kh,  g_kh);
    cudaGetSymbolAddress((void**)&vth, g_vth);
    cudaGetSymbolAddress((void**)&s,   g_s);
    cudaGetSymbolAddress((void**)&ph,  g_p);
    cudaGetSymbolAddress((void**)&xh,  g_xh);
    cudaGetSymbolAddress((void**)&wh,  g_wh);

    cudaFuncSetAttribute(gemm_fp16, cudaFuncAttributeMaxDynamicSharedMemorySize, SMEM_G);

    const size_t WSZ = (size_t)DMODEL * DMODEL;

    // 0) convert inputs to fp16
    {
        int n4x = BT_TOK * DMODEL / 4;
        f2h_kernel<<<(n4x + 255) / 256, 256>>>((const float4*)x, (__half2*)xh, n4x);
        int n4w = DMODEL * DMODEL / 4;
        f2h_kernel<<<(n4w + 255) / 256, 256>>>((const float4*)Wq, (__half2*)(wh + 0 * WSZ), n4w);
        f2h_kernel<<<(n4w + 255) / 256, 256>>>((const float4*)Wk, (__half2*)(wh + 1 * WSZ), n4w);
        f2h_kernel<<<(n4w + 255) / 256, 256>>>((const float4*)Wv, (__half2*)(wh + 2 * WSZ), n4w);
    }

    const dim3 blk(256);
    const size_t sQK = (size_t)TSEQ * DMODEL;
    const size_t sS  = (size_t)TSEQ * TSEQ;

    // 1) Q = x Wq^T + bq, K = x Wk^T + bk   [16384,1024] half out
    {
        dim3 g(DMODEL / 256, BT_TOK / 128, 1);
        gemm_fp16<<<g, blk, SMEM_G>>>(xh, DMODEL, 0, wh + 0 * WSZ, DMODEL, 0,
                                      qh, DMODEL, 0, bq, 1, 1.0f, DMODEL, 1);
        gemm_fp16<<<g, blk, SMEM_G>>>(xh, DMODEL, 0, wh + 1 * WSZ, DMODEL, 0,
                                      kh, DMODEL, 0, bk, 1, 1.0f, DMODEL, 1);
    }
    // 1b) Vt = Wv x^T + bv(per-row)   [1024, 16384] half out
    {
        dim3 g(BT_TOK / 256, DMODEL / 128, 1);
        gemm_fp16<<<g, blk, SMEM_G>>>(wh + 2 * WSZ, DMODEL, 0, xh, DMODEL, 0,
                                      vth, BT_TOK, 0, bv, 2, 1.0f, DMODEL, 1);
    }
    // 2) S = Q K^T * scale per batch   [2048,2048] fp32 out
    {
        dim3 g(TSEQ / 256, TSEQ / 128, NBATCH);
        gemm_fp16<<<g, blk, SMEM_G>>>(qh, DMODEL, sQK, kh, DMODEL, sQK,
                                      s, TSEQ, sS, nullptr, 0, SCALE, DMODEL, 0);
    }
    // 3) softmax rows -> fp16 P
    softmax2048<<<NBATCH * TSEQ, 256>>>(s, ph);

    // 4) O = P Vt^T per batch (fp32 out)
    {
        dim3 g(DMODEL / 256, TSEQ / 128, NBATCH);
        gemm_fp16<<<g, blk, SMEM_G>>>(ph, TSEQ, sS, vth, BT_TOK, (size_t)TSEQ,
                                      out, DMODEL, sQK, nullptr, 0, 1.0f, TSEQ, 0);
    }
}

// round 8
// speedup vs baseline: 1.0961x; 1.0961x over previous
#include <cuda_runtime.h>
#include <cuda_fp16.h>
#include <cstdint>
#include <cstddef>

// ---------------------------------------------------------------------------
// softmax(QK^T/32)V with Q/K/V = x W^T + b.
// fp16 mma.sync m16n8k16 (fp32 accum). All GEMMs NT (A[M,K]*B[N,K]^T);
// V produced transposed (Vt = Wv x^T + bv).
// R8 = R6 shape (128 thr, CTA 128x128, warp 64x64, occ 2) +
//      4-stage cp.async pipeline + ONE __syncthreads per K-chunk.
// ---------------------------------------------------------------------------

#define BT_TOK   16384
#define DMODEL   1024
#define TSEQ     2048
#define NBATCH   8
#define SCALE    0.03125f

// Scratch (device globals; allocation forbidden)
__device__ __half g_qh[(size_t)BT_TOK * DMODEL];          // 32 MB
__device__ __half g_kh[(size_t)BT_TOK * DMODEL];          // 32 MB
__device__ __half g_vth[(size_t)DMODEL * BT_TOK];         // 32 MB  Vt[f, tok]
__device__ float  g_s[(size_t)NBATCH * TSEQ * TSEQ];      // 128 MB scores fp32
__device__ __half g_p[(size_t)NBATCH * TSEQ * TSEQ];      // 64 MB  probs half
__device__ __half g_xh[(size_t)BT_TOK * DMODEL];          // 32 MB
__device__ __half g_wh[3][(size_t)DMODEL * DMODEL];       // 6 MB

// ---------------- helpers ----------------
__device__ __forceinline__ unsigned smem_u32(const void* p) {
    unsigned a;
    asm("{ .reg .u64 t; cvta.to.shared.u64 t, %1; cvt.u32.u64 %0, t; }" : "=r"(a) : "l"(p));
    return a;
}
__device__ __forceinline__ void cp16(unsigned saddr, const void* g) {
    asm volatile("cp.async.cg.shared.global [%0], [%1], 16;" :: "r"(saddr), "l"(g));
}
__device__ __forceinline__ void cp_commit() { asm volatile("cp.async.commit_group;"); }
template <int N> __device__ __forceinline__ void cp_wait() {
    asm volatile("cp.async.wait_group %0;" :: "n"(N));
}
__device__ __forceinline__ void ldsm_x4(uint32_t r[4], unsigned addr) {
    asm volatile("ldmatrix.sync.aligned.m8n8.x4.shared.b16 {%0,%1,%2,%3}, [%4];"
                 : "=r"(r[0]), "=r"(r[1]), "=r"(r[2]), "=r"(r[3]) : "r"(addr));
}
__device__ __forceinline__ void mma_fp16(float c[4], const uint32_t a[4],
                                         uint32_t b0, uint32_t b1) {
    asm volatile(
        "mma.sync.aligned.m16n8k16.row.col.f32.f16.f16.f32 "
        "{%0,%1,%2,%3}, {%4,%5,%6,%7}, {%8,%9}, {%0,%1,%2,%3};"
        : "+f"(c[0]), "+f"(c[1]), "+f"(c[2]), "+f"(c[3])
        : "r"(a[0]), "r"(a[1]), "r"(a[2]), "r"(a[3]), "r"(b0), "r"(b1));
}

// ---------------------------------------------------------------------------
// NT fp16 GEMM: C[M,N] = alpha * A[M,K] * B[N,K]^T (+ bias)
// CTA tile 128x128, K-chunk 32, 128 threads (4 warps 2x2, warp tile 64x64).
// 4-stage cp.async pipeline, one __syncthreads per chunk.
// Smem rows padded to 40 halves (80 B) -> ldmatrix conflict-free.
// bias_mode: 0 none, 1 per-col, 2 per-row.  out_half: C dtype.
// ---------------------------------------------------------------------------
#define ROWB   80                          // bytes per smem row (40 halves)
#define A_ST   (128 * ROWB)                // 10240 B per operand
#define STG    (2 * A_ST)                  // 20480 B per stage (A then B)
#define NSTAGE 4
#define SMEM_G (NSTAGE * STG)              // 81920 B

__global__ void __launch_bounds__(128, 2)
gemm_fp16(const __half* __restrict__ A, int lda, size_t sA,
          const __half* __restrict__ B, int ldb, size_t sB,
          void* __restrict__ Cv, int ldc, size_t sC,
          const float* __restrict__ bias, int bias_mode,
          float alpha, int K, int out_half)
{
    extern __shared__ __align__(128) char smem[];
    const unsigned sb = smem_u32(smem);

    const int tid  = threadIdx.x;
    const int lane = tid & 31;
    const int wid  = tid >> 5;
    const int wm   = (wid & 1) * 64;
    const int wn   = (wid >> 1) * 64;

    A += blockIdx.z * sA;
    B += blockIdx.z * sB;
    const int m0 = blockIdx.y * 128;
    const int n0 = blockIdx.x * 128;

    // per-lane ldmatrix offset (validated mapping from R6)
    const int li = lane >> 3, lr = lane & 7;
    const unsigned offL = (unsigned)((((li & 1) * 8 + lr) * 40 + (li >> 1) * 8) * 2);

    // staging coords: 4 x 16B per thread per operand (128 rows x 64 B)
    const int srow = tid >> 2, scol = (tid & 3) * 8;     // scol in halves

    float acc[4][8][4] = {};

    auto load_stage = [&](int st, int k0) {
        const __half* Ag = A + (size_t)m0 * lda + k0 + scol;
        const unsigned da = sb + st * STG + scol * 2;
#pragma unroll
        for (int p = 0; p < 4; p++)
            cp16(da + (srow + p * 32) * ROWB, Ag + (size_t)(srow + p * 32) * lda);
        const __half* Bg = B + (size_t)n0 * ldb + k0 + scol;
        const unsigned db = sb + st * STG + A_ST + scol * 2;
#pragma unroll
        for (int p = 0; p < 4; p++)
            cp16(db + (srow + p * 32) * ROWB, Bg + (size_t)(srow + p * 32) * ldb);
        cp_commit();
    };

    const int NK = K >> 5;                 // NK >= 32 here
    load_stage(0, 0);
    load_stage(1, 32);
    load_stage(2, 64);

    for (int i = 0; i < NK; i++) {
        const int st = i & 3;
        // chunk i's group must be complete:
        if (i <= NK - 3)      cp_wait<2>();
        else if (i == NK - 2) cp_wait<1>();
        else                  cp_wait<0>();
        __syncthreads();                   // all warps done with chunk i-1 too
        if (i + 3 < NK) load_stage((i + 3) & 3, (i + 3) * 32);

        const unsigned Ab = sb + st * STG + offL;
        const unsigned Bb = sb + st * STG + A_ST + offL;

#pragma unroll
        for (int ks = 0; ks < 2; ks++) {
            uint32_t a[4][4];
#pragma unroll
            for (int mt = 0; mt < 4; mt++)
                ldsm_x4(a[mt], Ab + (wm + mt * 16) * ROWB + ks * 32);
            uint32_t bq[4][4];
#pragma unroll
            for (int g = 0; g < 4; g++)
                ldsm_x4(bq[g], Bb + (wn + g * 16) * ROWB + ks * 32);
#pragma unroll
            for (int mt = 0; mt < 4; mt++)
#pragma unroll
                for (int nt = 0; nt < 8; nt++) {
                    const int g = nt >> 1;
                    const uint32_t b0 = (nt & 1) ? bq[g][1] : bq[g][0];
                    const uint32_t b1 = (nt & 1) ? bq[g][3] : bq[g][2];
                    mma_fp16(acc[mt][nt], a[mt], b0, b1);
                }
        }
    }

    // ---- epilogue (rows lane>>2 / +8, cols (lane&3)*2, +1) ----
    float* Cf = (float*)Cv + blockIdx.z * sC;
    __half* Ch = (__half*)Cv + blockIdx.z * sC;

#pragma unroll
    for (int nt = 0; nt < 8; nt++) {
        const int c = n0 + wn + nt * 8 + (lane & 3) * 2;
        float bx = 0.f, by = 0.f;
        if (bias_mode == 1) { bx = bias[c]; by = bias[c + 1]; }
#pragma unroll
        for (int mt = 0; mt < 4; mt++) {
            const int r = m0 + wm + mt * 16 + (lane >> 2);
            float r0x = acc[mt][nt][0] * alpha, r0y = acc[mt][nt][1] * alpha;
            float r1x = acc[mt][nt][2] * alpha, r1y = acc[mt][nt][3] * alpha;
            if (bias_mode == 1) { r0x += bx; r0y += by; r1x += bx; r1y += by; }
            else if (bias_mode == 2) {
                const float b0 = bias[r], b1 = bias[r + 8];
                r0x += b0; r0y += b0; r1x += b1; r1y += b1;
            }
            if (out_half) {
                *(__half2*)(Ch + (size_t)r * ldc + c)       = __floats2half2_rn(r0x, r0y);
                *(__half2*)(Ch + (size_t)(r + 8) * ldc + c) = __floats2half2_rn(r1x, r1y);
            } else {
                *(float2*)(Cf + (size_t)r * ldc + c)       = make_float2(r0x, r0y);
                *(float2*)(Cf + (size_t)(r + 8) * ldc + c) = make_float2(r1x, r1y);
            }
        }
    }
}

// ---------------------------------------------------------------------------
// fp32 -> fp16 conversion (rn).
// ---------------------------------------------------------------------------
__global__ void __launch_bounds__(256)
f2h_kernel(const float4* __restrict__ in, __half2* __restrict__ out, int n4)
{
    int i = blockIdx.x * blockDim.x + threadIdx.x;
    if (i < n4) {
        float4 v = in[i];
        out[2 * i]     = __floats2half2_rn(v.x, v.y);
        out[2 * i + 1] = __floats2half2_rn(v.z, v.w);
    }
}

// ---------------------------------------------------------------------------
// Row softmax over 2048-wide fp32 rows -> fp16 probabilities.
// ---------------------------------------------------------------------------
__global__ void __launch_bounds__(256)
softmax2048(const float* __restrict__ S, __half* __restrict__ P)
{
    const int row = blockIdx.x;
    const float* p = S + (size_t)row * 2048;
    __half* o = P + (size_t)row * 2048;
    const int t = threadIdx.x;

    float v[8];
#pragma unroll
    for (int i = 0; i < 8; i++) v[i] = p[t + i * 256];

    float m = v[0];
#pragma unroll
    for (int i = 1; i < 8; i++) m = fmaxf(m, v[i]);
#pragma unroll
    for (int o2 = 16; o2; o2 >>= 1) m = fmaxf(m, __shfl_xor_sync(0xffffffffu, m, o2));

    __shared__ float red[8];
    if ((t & 31) == 0) red[t >> 5] = m;
    __syncthreads();
#pragma unroll
    for (int i = 0; i < 8; i++) m = fmaxf(m, red[i]);

    float s = 0.0f;
#pragma unroll
    for (int i = 0; i < 8; i++) { v[i] = __expf(v[i] - m); s += v[i]; }
#pragma unroll
    for (int o2 = 16; o2; o2 >>= 1) s += __shfl_xor_sync(0xffffffffu, s, o2);

    __syncthreads();
    if ((t & 31) == 0) red[t >> 5] = s;
    __syncthreads();
    s = 0.0f;
#pragma unroll
    for (int i = 0; i < 8; i++) s += red[i];

    const float inv = 1.0f / s;
#pragma unroll
    for (int i = 0; i < 8; i++) o[t + i * 256] = __float2half_rn(v[i] * inv);
}

// ---------------------------------------------------------------------------
// Launch pipeline (graph-capturable: kernels only)
// ---------------------------------------------------------------------------
extern "C" void kernel_launch(void* const* d_in, const int* in_sizes, int n_in,
                              void* d_out, int out_size)
{
    (void)in_sizes; (void)n_in; (void)out_size;
    const float* x  = (const float*)d_in[0];
    const float* Wq = (const float*)d_in[1];
    const float* bq = (const float*)d_in[2];
    const float* Wk = (const float*)d_in[3];
    const float* bk = (const float*)d_in[4];
    const float* Wv = (const float*)d_in[5];
    const float* bv = (const float*)d_in[6];
    float* out = (float*)d_out;

    __half *qh, *kh, *vth, *ph, *xh, *wh;
    float* s;
    cudaGetSymbolAddress((void**)&qh,  g_qh);
    cudaGetSymbolAddress((void**)&kh,  g_kh);
    cudaGetSymbolAddress((void**)&vth, g_vth);
    cudaGetSymbolAddress((void**)&s,   g_s);
    cudaGetSymbolAddress((void**)&ph,  g_p);
    cudaGetSymbolAddress((void**)&xh,  g_xh);
    cudaGetSymbolAddress((void**)&wh,  g_wh);

    cudaFuncSetAttribute(gemm_fp16, cudaFuncAttributeMaxDynamicSharedMemorySize, SMEM_G);

    const size_t WSZ = (size_t)DMODEL * DMODEL;

    // 0) convert inputs to fp16
    {
        int n4x = BT_TOK * DMODEL / 4;
        f2h_kernel<<<(n4x + 255) / 256, 256>>>((const float4*)x, (__half2*)xh, n4x);
        int n4w = DMODEL * DMODEL / 4;
        f2h_kernel<<<(n4w + 255) / 256, 256>>>((const float4*)Wq, (__half2*)(wh + 0 * WSZ), n4w);
        f2h_kernel<<<(n4w + 255) / 256, 256>>>((const float4*)Wk, (__half2*)(wh + 1 * WSZ), n4w);
        f2h_kernel<<<(n4w + 255) / 256, 256>>>((const float4*)Wv, (__half2*)(wh + 2 * WSZ), n4w);
    }

    const dim3 blk(128);
    const size_t sQK = (size_t)TSEQ * DMODEL;
    const size_t sS  = (size_t)TSEQ * TSEQ;

    // 1) Q = x Wq^T + bq, K = x Wk^T + bk   [16384,1024] half out
    {
        dim3 g(DMODEL / 128, BT_TOK / 128, 1);
        gemm_fp16<<<g, blk, SMEM_G>>>(xh, DMODEL, 0, wh + 0 * WSZ, DMODEL, 0,
                                      qh, DMODEL, 0, bq, 1, 1.0f, DMODEL, 1);
        gemm_fp16<<<g, blk, SMEM_G>>>(xh, DMODEL, 0, wh + 1 * WSZ, DMODEL, 0,
                                      kh, DMODEL, 0, bk, 1, 1.0f, DMODEL, 1);
    }
    // 1b) Vt = Wv x^T + bv(per-row)   [1024, 16384] half out
    {
        dim3 g(BT_TOK / 128, DMODEL / 128, 1);
        gemm_fp16<<<g, blk, SMEM_G>>>(wh + 2 * WSZ, DMODEL, 0, xh, DMODEL, 0,
                                      vth, BT_TOK, 0, bv, 2, 1.0f, DMODEL, 1);
    }
    // 2) S = Q K^T * scale per batch   [2048,2048] fp32 out
    {
        dim3 g(TSEQ / 128, TSEQ / 128, NBATCH);
        gemm_fp16<<<g, blk, SMEM_G>>>(qh, DMODEL, sQK, kh, DMODEL, sQK,
                                      s, TSEQ, sS, nullptr, 0, SCALE, DMODEL, 0);
    }
    // 3) softmax rows -> fp16 P
    softmax2048<<<NBATCH * TSEQ, 256>>>(s, ph);

    // 4) O = P Vt^T per batch (fp32 out)
    {
        dim3 g(DMODEL / 128, TSEQ / 128, NBATCH);
        gemm_fp16<<<g, blk, SMEM_G>>>(ph, TSEQ, sS, vth, BT_TOK, (size_t)TSEQ,
                                      out, DMODEL, sQK, nullptr, 0, 1.0f, TSEQ, 0);
    }
}

// round 12
// speedup vs baseline: 1.1102x; 1.0129x over previous
#include <cuda_runtime.h>
#include <cuda_fp16.h>
#include <cstdint>
#include <cstddef>

// ---------------------------------------------------------------------------
// softmax(QK^T/32)V with Q/K/V = x W^T + b.
// fp16 mma.sync m16n8k16 (fp32 accum). All GEMMs NT (A[M,K]*B[N,K]^T);
// V produced transposed (Vt = Wv x^T + bv).
// R10 = R9 resubmission (infra failure last round, kernel never evaluated):
//   R8 + front-loaded fragment LDSMs (no ks-boundary bubbles)
//      + fp16 scores buffer with in-place softmax.
// ---------------------------------------------------------------------------

#define BT_TOK   16384
#define DMODEL   1024
#define TSEQ     2048
#define NBATCH   8
#define SCALE    0.03125f

// Scratch (device globals; allocation forbidden)
__device__ __half g_qh[(size_t)BT_TOK * DMODEL];          // 32 MB
__device__ __half g_kh[(size_t)BT_TOK * DMODEL];          // 32 MB
__device__ __half g_vth[(size_t)DMODEL * BT_TOK];         // 32 MB  Vt[f, tok]
__device__ __half g_p[(size_t)NBATCH * TSEQ * TSEQ];      // 64 MB  scores->probs (in place)
__device__ __half g_xh[(size_t)BT_TOK * DMODEL];          // 32 MB
__device__ __half g_wh[3][(size_t)DMODEL * DMODEL];       // 6 MB

// ---------------- helpers ----------------
__device__ __forceinline__ unsigned smem_u32(const void* p) {
    unsigned a;
    asm("{ .reg .u64 t; cvta.to.shared.u64 t, %1; cvt.u32.u64 %0, t; }" : "=r"(a) : "l"(p));
    return a;
}
__device__ __forceinline__ void cp16(unsigned saddr, const void* g) {
    asm volatile("cp.async.cg.shared.global [%0], [%1], 16;" :: "r"(saddr), "l"(g));
}
__device__ __forceinline__ void cp_commit() { asm volatile("cp.async.commit_group;"); }
template <int N> __device__ __forceinline__ void cp_wait() {
    asm volatile("cp.async.wait_group %0;" :: "n"(N));
}
__device__ __forceinline__ void ldsm_x4(uint32_t r[4], unsigned addr) {
    asm volatile("ldmatrix.sync.aligned.m8n8.x4.shared.b16 {%0,%1,%2,%3}, [%4];"
                 : "=r"(r[0]), "=r"(r[1]), "=r"(r[2]), "=r"(r[3]) : "r"(addr));
}
__device__ __forceinline__ void mma_fp16(float c[4], const uint32_t a[4],
                                         uint32_t b0, uint32_t b1) {
    asm volatile(
        "mma.sync.aligned.m16n8k16.row.col.f32.f16.f16.f32 "
        "{%0,%1,%2,%3}, {%4,%5,%6,%7}, {%8,%9}, {%0,%1,%2,%3};"
        : "+f"(c[0]), "+f"(c[1]), "+f"(c[2]), "+f"(c[3])
        : "r"(a[0]), "r"(a[1]), "r"(a[2]), "r"(a[3]), "r"(b0), "r"(b1));
}

// ---------------------------------------------------------------------------
// NT fp16 GEMM: C[M,N] = alpha * A[M,K] * B[N,K]^T (+ bias)
// CTA tile 128x128, K-chunk 32, 128 threads (4 warps 2x2, warp tile 64x64).
// 4-stage cp.async, one __syncthreads per chunk, fragments front-loaded.
// Smem rows padded to 40 halves (80 B) -> ldmatrix conflict-free.
// bias_mode: 0 none, 1 per-col, 2 per-row.  out_half: C dtype.
// ---------------------------------------------------------------------------
#define ROWB   80                          // bytes per smem row (40 halves)
#define A_ST   (128 * ROWB)                // 10240 B per operand
#define STG    (2 * A_ST)                  // 20480 B per stage
#define NSTAGE 4
#define SMEM_G (NSTAGE * STG)              // 81920 B

__global__ void __launch_bounds__(128, 2)
gemm_fp16(const __half* __restrict__ A, int lda, size_t sA,
          const __half* __restrict__ B, int ldb, size_t sB,
          void* __restrict__ Cv, int ldc, size_t sC,
          const float* __restrict__ bias, int bias_mode,
          float alpha, int K, int out_half)
{
    extern __shared__ __align__(128) char smem[];
    const unsigned sb = smem_u32(smem);

    const int tid  = threadIdx.x;
    const int lane = tid & 31;
    const int wid  = tid >> 5;
    const int wm   = (wid & 1) * 64;
    const int wn   = (wid >> 1) * 64;

    A += blockIdx.z * sA;
    B += blockIdx.z * sB;
    const int m0 = blockIdx.y * 128;
    const int n0 = blockIdx.x * 128;

    // per-lane ldmatrix offset (validated mapping)
    const int li = lane >> 3, lr = lane & 7;
    const unsigned offL = (unsigned)((((li & 1) * 8 + lr) * 40 + (li >> 1) * 8) * 2);

    // staging coords: 4 x 16B per thread per operand (128 rows x 64 B)
    const int srow = tid >> 2, scol = (tid & 3) * 8;

    float acc[4][8][4] = {};

    auto load_stage = [&](int st, int k0) {
        const __half* Ag = A + (size_t)m0 * lda + k0 + scol;
        const unsigned da = sb + st * STG + scol * 2;
#pragma unroll
        for (int p = 0; p < 4; p++)
            cp16(da + (srow + p * 32) * ROWB, Ag + (size_t)(srow + p * 32) * lda);
        const __half* Bg = B + (size_t)n0 * ldb + k0 + scol;
        const unsigned db = sb + st * STG + A_ST + scol * 2;
#pragma unroll
        for (int p = 0; p < 4; p++)
            cp16(db + (srow + p * 32) * ROWB, Bg + (size_t)(srow + p * 32) * ldb);
        cp_commit();
    };

    const int NK = K >> 5;
    load_stage(0, 0);
    load_stage(1, 32);
    load_stage(2, 64);

    for (int i = 0; i < NK; i++) {
        const int st = i & 3;
        if (i <= NK - 3)      cp_wait<2>();
        else if (i == NK - 2) cp_wait<1>();
        else                  cp_wait<0>();
        __syncthreads();
        if (i + 3 < NK) load_stage((i + 3) & 3, (i + 3) * 32);

        const unsigned Ab = sb + st * STG + offL;
        const unsigned Bb = sb + st * STG + A_ST + offL;

        // ---- front-load ALL fragments for both ks-steps ----
        uint32_t a2[2][4][4], b2[2][4][4];
#pragma unroll
        for (int ks = 0; ks < 2; ks++) {
#pragma unroll
            for (int mt = 0; mt < 4; mt++)
                ldsm_x4(a2[ks][mt], Ab + (wm + mt * 16) * ROWB + ks * 32);
#pragma unroll
            for (int g = 0; g < 4; g++)
                ldsm_x4(b2[ks][g], Bb + (wn + g * 16) * ROWB + ks * 32);
        }
        // ---- uninterrupted HMMA stream ----
#pragma unroll
        for (int ks = 0; ks < 2; ks++)
#pragma unroll
            for (int mt = 0; mt < 4; mt++)
#pragma unroll
                for (int nt = 0; nt < 8; nt++) {
                    const int g = nt >> 1;
                    const uint32_t b0 = (nt & 1) ? b2[ks][g][1] : b2[ks][g][0];
                    const uint32_t b1 = (nt & 1) ? b2[ks][g][3] : b2[ks][g][2];
                    mma_fp16(acc[mt][nt], a2[ks][mt], b0, b1);
                }
    }

    // ---- epilogue (rows lane>>2 / +8, cols (lane&3)*2, +1) ----
    float* Cf = (float*)Cv + blockIdx.z * sC;
    __half* Ch = (__half*)Cv + blockIdx.z * sC;

#pragma unroll
    for (int nt = 0; nt < 8; nt++) {
        const int c = n0 + wn + nt * 8 + (lane & 3) * 2;
        float bx = 0.f, by = 0.f;
        if (bias_mode == 1) { bx = bias[c]; by = bias[c + 1]; }
#pragma unroll
        for (int mt = 0; mt < 4; mt++) {
            const int r = m0 + wm + mt * 16 + (lane >> 2);
            float r0x = acc[mt][nt][0] * alpha, r0y = acc[mt][nt][1] * alpha;
            float r1x = acc[mt][nt][2] * alpha, r1y = acc[mt][nt][3] * alpha;
            if (bias_mode == 1) { r0x += bx; r0y += by; r1x += bx; r1y += by; }
            else if (bias_mode == 2) {
                const float b0 = bias[r], b1 = bias[r + 8];
                r0x += b0; r0y += b0; r1x += b1; r1y += b1;
            }
            if (out_half) {
                *(__half2*)(Ch + (size_t)r * ldc + c)       = __floats2half2_rn(r0x, r0y);
                *(__half2*)(Ch + (size_t)(r + 8) * ldc + c) = __floats2half2_rn(r1x, r1y);
            } else {
                *(float2*)(Cf + (size_t)r * ldc + c)       = make_float2(r0x, r0y);
                *(float2*)(Cf + (size_t)(r + 8) * ldc + c) = make_float2(r1x, r1y);
            }
        }
    }
}

// ---------------------------------------------------------------------------
// fp32 -> fp16 conversion (rn).
// ---------------------------------------------------------------------------
__global__ void __launch_bounds__(256)
f2h_kernel(const float4* __restrict__ in, __half2* __restrict__ out, int n4)
{
    int i = blockIdx.x * blockDim.x + threadIdx.x;
    if (i < n4) {
        float4 v = in[i];
        out[2 * i]     = __floats2half2_rn(v.x, v.y);
        out[2 * i + 1] = __floats2half2_rn(v.z, v.w);
    }
}

// ---------------------------------------------------------------------------
// In-place row softmax over 2048-wide fp16 rows (fp32 math inside).
// ---------------------------------------------------------------------------
__global__ void __launch_bounds__(256)
softmax2048(__half* __restrict__ S)
{
    const int row = blockIdx.x;
    __half* p = S + (size_t)row * 2048;
    const int t = threadIdx.x;

    float v[8];
    {
        __half2* p2 = (__half2*)p;
#pragma unroll
        for (int i = 0; i < 4; i++) {
            float2 f = __half22float2(p2[t + i * 256]);
            v[2 * i] = f.x; v[2 * i + 1] = f.y;
        }
    }

    float m = v[0];
#pragma unroll
    for (int i = 1; i < 8; i++) m = fmaxf(m, v[i]);
#pragma unroll
    for (int o2 = 16; o2; o2 >>= 1) m = fmaxf(m, __shfl_xor_sync(0xffffffffu, m, o2));

    __shared__ float red[8];
    if ((t & 31) == 0) red[t >> 5] = m;
    __syncthreads();
#pragma unroll
    for (int i = 0; i < 8; i++) m = fmaxf(m, red[i]);

    float s = 0.0f;
#pragma unroll
    for (int i = 0; i < 8; i++) { v[i] = __expf(v[i] - m); s += v[i]; }
#pragma unroll
    for (int o2 = 16; o2; o2 >>= 1) s += __shfl_xor_sync(0xffffffffu, s, o2);

    __syncthreads();
    if ((t & 31) == 0) red[t >> 5] = s;
    __syncthreads();
    s = 0.0f;
#pragma unroll
    for (int i = 0; i < 8; i++) s += red[i];

    const float inv = 1.0f / s;
    {
        __half2* p2 = (__half2*)p;
#pragma unroll
        for (int i = 0; i < 4; i++)
            p2[t + i * 256] = __floats2half2_rn(v[2 * i] * inv, v[2 * i + 1] * inv);
    }
}

// ---------------------------------------------------------------------------
// Launch pipeline (graph-capturable: kernels only)
// ---------------------------------------------------------------------------
extern "C" void kernel_launch(void* const* d_in, const int* in_sizes, int n_in,
                              void* d_out, int out_size)
{
    (void)in_sizes; (void)n_in; (void)out_size;
    const float* x  = (const float*)d_in[0];
    const float* Wq = (const float*)d_in[1];
    const float* bq = (const float*)d_in[2];
    const float* Wk = (const float*)d_in[3];
    const float* bk = (const float*)d_in[4];
    const float* Wv = (const float*)d_in[5];
    const float* bv = (const float*)d_in[6];
    float* out = (float*)d_out;

    __half *qh, *kh, *vth, *ph, *xh, *wh;
    cudaGetSymbolAddress((void**)&qh,  g_qh);
    cudaGetSymbolAddress((void**)&kh,  g_kh);
    cudaGetSymbolAddress((void**)&vth, g_vth);
    cudaGetSymbolAddress((void**)&ph,  g_p);
    cudaGetSymbolAddress((void**)&xh,  g_xh);
    cudaGetSymbolAddress((void**)&wh,  g_wh);

    cudaFuncSetAttribute(gemm_fp16, cudaFuncAttributeMaxDynamicSharedMemorySize, SMEM_G);

    const size_t WSZ = (size_t)DMODEL * DMODEL;

    // 0) convert inputs to fp16
    {
        int n4x = BT_TOK * DMODEL / 4;
        f2h_kernel<<<(n4x + 255) / 256, 256>>>((const float4*)x, (__half2*)xh, n4x);
        int n4w = DMODEL * DMODEL / 4;
        f2h_kernel<<<(n4w + 255) / 256, 256>>>((const float4*)Wq, (__half2*)(wh + 0 * WSZ), n4w);
        f2h_kernel<<<(n4w + 255) / 256, 256>>>((const float4*)Wk, (__half2*)(wh + 1 * WSZ), n4w);
        f2h_kernel<<<(n4w + 255) / 256, 256>>>((const float4*)Wv, (__half2*)(wh + 2 * WSZ), n4w);
    }

    const dim3 blk(128);
    const size_t sQK = (size_t)TSEQ * DMODEL;
    const size_t sS  = (size_t)TSEQ * TSEQ;

    // 1) Q = x Wq^T + bq, K = x Wk^T + bk   [16384,1024] half out
    {
        dim3 g(DMODEL / 128, BT_TOK / 128, 1);
        gemm_fp16<<<g, blk, SMEM_G>>>(xh, DMODEL, 0, wh + 0 * WSZ, DMODEL, 0,
                                      qh, DMODEL, 0, bq, 1, 1.0f, DMODEL, 1);
        gemm_fp16<<<g, blk, SMEM_G>>>(xh, DMODEL, 0, wh + 1 * WSZ, DMODEL, 0,
                                      kh, DMODEL, 0, bk, 1, 1.0f, DMODEL, 1);
    }
    // 1b) Vt = Wv x^T + bv(per-row)   [1024, 16384] half out
    {
        dim3 g(BT_TOK / 128, DMODEL / 128, 1);
        gemm_fp16<<<g, blk, SMEM_G>>>(wh + 2 * WSZ, DMODEL, 0, xh, DMODEL, 0,
                                      vth, BT_TOK, 0, bv, 2, 1.0f, DMODEL, 1);
    }
    // 2) S = Q K^T * scale per batch   [2048,2048] fp16 out (scores)
    {
        dim3 g(TSEQ / 128, TSEQ / 128, NBATCH);
        gemm_fp16<<<g, blk, SMEM_G>>>(qh, DMODEL, sQK, kh, DMODEL, sQK,
                                      ph, TSEQ, sS, nullptr, 0, SCALE, DMODEL, 1);
    }
    // 3) softmax rows in place (fp16 buffer)
    softmax2048<<<NBATCH * TSEQ, 256>>>(ph);

    // 4) O = P Vt^T per batch (fp32 out)
    {
        dim3 g(DMODEL / 128, TSEQ / 128, NBATCH);
        gemm_fp16<<<g, blk, SMEM_G>>>(ph, TSEQ, sS, vth, BT_TOK, (size_t)TSEQ,
                                      out, DMODEL, sQK, nullptr, 0, 1.0f, TSEQ, 0);
    }
}

// round 17
// speedup vs baseline: 1.1288x; 1.0168x over previous
#include <cuda_runtime.h>
#include <cuda_fp16.h>
#include <cstdint>
#include <cstddef>

// ---------------------------------------------------------------------------
// softmax(QK^T/32)V with Q/K/V = x W^T + b.
// fp16 mma.sync m16n8k16 (fp32 accum). All GEMMs NT (A[M,K]*B[N,K]^T);
// V produced transposed (Vt = Wv x^T + bv).
// R16 = R13/R14 resubmission (infra failures; kernel never evaluated):
//   occupancy experiment — 256 threads/CTA (8 warps, warp tile 64x32),
//   occ 2 => 16 warps/SM = 4 per SMSP (vs 2 in all prior rounds).
//   3-stage cp.async, one __syncthreads per chunk. fp16 scores in place.
// ---------------------------------------------------------------------------

#define BT_TOK   16384
#define DMODEL   1024
#define TSEQ     2048
#define NBATCH   8
#define SCALE    0.03125f

// Scratch (device globals; allocation forbidden)
__device__ __half g_qh[(size_t)BT_TOK * DMODEL];          // 32 MB
__device__ __half g_kh[(size_t)BT_TOK * DMODEL];          // 32 MB
__device__ __half g_vth[(size_t)DMODEL * BT_TOK];         // 32 MB  Vt[f, tok]
__device__ __half g_p[(size_t)NBATCH * TSEQ * TSEQ];      // 64 MB  scores->probs (in place)
__device__ __half g_xh[(size_t)BT_TOK * DMODEL];          // 32 MB
__device__ __half g_wh[3][(size_t)DMODEL * DMODEL];       // 6 MB

// ---------------- helpers ----------------
__device__ __forceinline__ unsigned smem_u32(const void* p) {
    unsigned a;
    asm("{ .reg .u64 t; cvta.to.shared.u64 t, %1; cvt.u32.u64 %0, t; }" : "=r"(a) : "l"(p));
    return a;
}
__device__ __forceinline__ void cp16(unsigned saddr, const void* g) {
    asm volatile("cp.async.cg.shared.global [%0], [%1], 16;" :: "r"(saddr), "l"(g));
}
__device__ __forceinline__ void cp_commit() { asm volatile("cp.async.commit_group;"); }
template <int N> __device__ __forceinline__ void cp_wait() {
    asm volatile("cp.async.wait_group %0;" :: "n"(N));
}
__device__ __forceinline__ void ldsm_x4(uint32_t r[4], unsigned addr) {
    asm volatile("ldmatrix.sync.aligned.m8n8.x4.shared.b16 {%0,%1,%2,%3}, [%4];"
                 : "=r"(r[0]), "=r"(r[1]), "=r"(r[2]), "=r"(r[3]) : "r"(addr));
}
__device__ __forceinline__ void mma_fp16(float c[4], const uint32_t a[4],
                                         uint32_t b0, uint32_t b1) {
    asm volatile(
        "mma.sync.aligned.m16n8k16.row.col.f32.f16.f16.f32 "
        "{%0,%1,%2,%3}, {%4,%5,%6,%7}, {%8,%9}, {%0,%1,%2,%3};"
        : "+f"(c[0]), "+f"(c[1]), "+f"(c[2]), "+f"(c[3])
        : "r"(a[0]), "r"(a[1]), "r"(a[2]), "r"(a[3]), "r"(b0), "r"(b1));
}

// ---------------------------------------------------------------------------
// NT fp16 GEMM: C[M,N] = alpha * A[M,K] * B[N,K]^T (+ bias)
// CTA tile 128x128, K-chunk 32, 256 threads: 8 warps (2M x 4N), warp 64x32.
// 3-stage cp.async, one __syncthreads per chunk.
// Smem rows padded to 40 halves (80 B) -> ldmatrix conflict-free.
// bias_mode: 0 none, 1 per-col, 2 per-row.  out_half: C dtype.
// ---------------------------------------------------------------------------
#define ROWB   80                          // bytes per smem row (40 halves)
#define A_ST   (128 * ROWB)                // 10240 B per operand
#define STG    (2 * A_ST)                  // 20480 B per stage
#define NSTAGE 3
#define SMEM_G (NSTAGE * STG)              // 61440 B

__global__ void __launch_bounds__(256, 2)
gemm_fp16(const __half* __restrict__ A, int lda, size_t sA,
          const __half* __restrict__ B, int ldb, size_t sB,
          void* __restrict__ Cv, int ldc, size_t sC,
          const float* __restrict__ bias, int bias_mode,
          float alpha, int K, int out_half)
{
    extern __shared__ __align__(128) char smem[];
    const unsigned sb = smem_u32(smem);

    const int tid  = threadIdx.x;
    const int lane = tid & 31;
    const int wid  = tid >> 5;            // 0..7
    const int wm   = (wid & 1) * 64;      // 2 M positions
    const int wn   = (wid >> 1) * 32;     // 4 N positions of 32

    A += blockIdx.z * sA;
    B += blockIdx.z * sB;
    const int m0 = blockIdx.y * 128;
    const int n0 = blockIdx.x * 128;

    // per-lane ldmatrix offset (validated mapping)
    const int li = lane >> 3, lr = lane & 7;
    const unsigned offL = (unsigned)((((li & 1) * 8 + lr) * 40 + (li >> 1) * 8) * 2);

    // staging: 2 x 16B per thread per operand (128 rows x 64 B, 256 threads)
    const int srow = tid >> 2, scol = (tid & 3) * 8;   // srow 0..63, scol halves

    float acc[4][4][4] = {};                 // 64 regs

    auto load_stage = [&](int st, int k0) {
        const __half* Ag = A + (size_t)m0 * lda + k0 + scol;
        const unsigned da = sb + st * STG + scol * 2;
#pragma unroll
        for (int p = 0; p < 2; p++)
            cp16(da + (srow + p * 64) * ROWB, Ag + (size_t)(srow + p * 64) * lda);
        const __half* Bg = B + (size_t)n0 * ldb + k0 + scol;
        const unsigned db = sb + st * STG + A_ST + scol * 2;
#pragma unroll
        for (int p = 0; p < 2; p++)
            cp16(db + (srow + p * 64) * ROWB, Bg + (size_t)(srow + p * 64) * ldb);
        cp_commit();
    };

    const int NK = K >> 5;
    load_stage(0, 0);
    load_stage(1, 32);

    for (int i = 0; i < NK; i++) {
        const int st = i % NSTAGE;
        if (i < NK - 1) cp_wait<1>(); else cp_wait<0>();
        __syncthreads();                     // stage i ready; chunk i-1 consumed
        if (i + 2 < NK) load_stage((i + 2) % NSTAGE, (i + 2) * 32);

        const unsigned Ab = sb + st * STG + offL;
        const unsigned Bb = sb + st * STG + A_ST + offL;

#pragma unroll
        for (int ks = 0; ks < 2; ks++) {
            uint32_t a[4][4];
#pragma unroll
            for (int mt = 0; mt < 4; mt++)
                ldsm_x4(a[mt], Ab + (wm + mt * 16) * ROWB + ks * 32);
            uint32_t bq[2][4];
#pragma unroll
            for (int g = 0; g < 2; g++)
                ldsm_x4(bq[g], Bb + (wn + g * 16) * ROWB + ks * 32);
#pragma unroll
            for (int mt = 0; mt < 4; mt++)
#pragma unroll
                for (int nt = 0; nt < 4; nt++) {
                    const int g = nt >> 1;
                    const uint32_t b0 = (nt & 1) ? bq[g][1] : bq[g][0];
                    const uint32_t b1 = (nt & 1) ? bq[g][3] : bq[g][2];
                    mma_fp16(acc[mt][nt], a[mt], b0, b1);
                }
        }
    }

    // ---- epilogue (rows lane>>2 / +8, cols (lane&3)*2, +1) ----
    float* Cf = (float*)Cv + blockIdx.z * sC;
    __half* Ch = (__half*)Cv + blockIdx.z * sC;

#pragma unroll
    for (int nt = 0; nt < 4; nt++) {
        const int c = n0 + wn + nt * 8 + (lane & 3) * 2;
        float bx = 0.f, by = 0.f;
        if (bias_mode == 1) { bx = bias[c]; by = bias[c + 1]; }
#pragma unroll
        for (int mt = 0; mt < 4; mt++) {
            const int r = m0 + wm + mt * 16 + (lane >> 2);
            float r0x = acc[mt][nt][0] * alpha, r0y = acc[mt][nt][1] * alpha;
            float r1x = acc[mt][nt][2] * alpha, r1y = acc[mt][nt][3] * alpha;
            if (bias_mode == 1) { r0x += bx; r0y += by; r1x += bx; r1y += by; }
            else if (bias_mode == 2) {
                const float b0 = bias[r], b1 = bias[r + 8];
                r0x += b0; r0y += b0; r1x += b1; r1y += b1;
            }
            if (out_half) {
                *(__half2*)(Ch + (size_t)r * ldc + c)       = __floats2half2_rn(r0x, r0y);
                *(__half2*)(Ch + (size_t)(r + 8) * ldc + c) = __floats2half2_rn(r1x, r1y);
            } else {
                *(float2*)(Cf + (size_t)r * ldc + c)       = make_float2(r0x, r0y);
                *(float2*)(Cf + (size_t)(r + 8) * ldc + c) = make_float2(r1x, r1y);
            }
        }
    }
}

// ---------------------------------------------------------------------------
// fp32 -> fp16 conversion (rn).
// ---------------------------------------------------------------------------
__global__ void __launch_bounds__(256)
f2h_kernel(const float4* __restrict__ in, __half2* __restrict__ out, int n4)
{
    int i = blockIdx.x * blockDim.x + threadIdx.x;
    if (i < n4) {
        float4 v = in[i];
        out[2 * i]     = __floats2half2_rn(v.x, v.y);
        out[2 * i + 1] = __floats2half2_rn(v.z, v.w);
    }
}

// ---------------------------------------------------------------------------
// In-place row softmax over 2048-wide fp16 rows (fp32 math inside).
// ---------------------------------------------------------------------------
__global__ void __launch_bounds__(256)
softmax2048(__half* __restrict__ S)
{
    const int row = blockIdx.x;
    __half* p = S + (size_t)row * 2048;
    const int t = threadIdx.x;

    float v[8];
    {
        __half2* p2 = (__half2*)p;
#pragma unroll
        for (int i = 0; i < 4; i++) {
            float2 f = __half22float2(p2[t + i * 256]);
            v[2 * i] = f.x; v[2 * i + 1] = f.y;
        }
    }

    float m = v[0];
#pragma unroll
    for (int i = 1; i < 8; i++) m = fmaxf(m, v[i]);
#pragma unroll
    for (int o2 = 16; o2; o2 >>= 1) m = fmaxf(m, __shfl_xor_sync(0xffffffffu, m, o2));

    __shared__ float red[8];
    if ((t & 31) == 0) red[t >> 5] = m;
    __syncthreads();
#pragma unroll
    for (int i = 0; i < 8; i++) m = fmaxf(m, red[i]);

    float s = 0.0f;
#pragma unroll
    for (int i = 0; i < 8; i++) { v[i] = __expf(v[i] - m); s += v[i]; }
#pragma unroll
    for (int o2 = 16; o2; o2 >>= 1) s += __shfl_xor_sync(0xffffffffu, s, o2);

    __syncthreads();
    if ((t & 31) == 0) red[t >> 5] = s;
    __syncthreads();
    s = 0.0f;
#pragma unroll
    for (int i = 0; i < 8; i++) s += red[i];

    const float inv = 1.0f / s;
    {
        __half2* p2 = (__half2*)p;
#pragma unroll
        for (int i = 0; i < 4; i++)
            p2[t + i * 256] = __floats2half2_rn(v[2 * i] * inv, v[2 * i + 1] * inv);
    }
}

// ---------------------------------------------------------------------------
// Launch pipeline (graph-capturable: kernels only)
// ---------------------------------------------------------------------------
extern "C" void kernel_launch(void* const* d_in, const int* in_sizes, int n_in,
                              void* d_out, int out_size)
{
    (void)in_sizes; (void)n_in; (void)out_size;
    const float* x  = (const float*)d_in[0];
    const float* Wq = (const float*)d_in[1];
    const float* bq = (const float*)d_in[2];
    const float* Wk = (const float*)d_in[3];
    const float* bk = (const float*)d_in[4];
    const float* Wv = (const float*)d_in[5];
    const float* bv = (const float*)d_in[6];
    float* out = (float*)d_out;

    __half *qh, *kh, *vth, *ph, *xh, *wh;
    cudaGetSymbolAddress((void**)&qh,  g_qh);
    cudaGetSymbolAddress((void**)&kh,  g_kh);
    cudaGetSymbolAddress((void**)&vth, g_vth);
    cudaGetSymbolAddress((void**)&ph,  g_p);
    cudaGetSymbolAddress((void**)&xh,  g_xh);
    cudaGetSymbolAddress((void**)&wh,  g_wh);

    cudaFuncSetAttribute(gemm_fp16, cudaFuncAttributeMaxDynamicSharedMemorySize, SMEM_G);

    const size_t WSZ = (size_t)DMODEL * DMODEL;

    // 0) convert inputs to fp16
    {
        int n4x = BT_TOK * DMODEL / 4;
        f2h_kernel<<<(n4x + 255) / 256, 256>>>((const float4*)x, (__half2*)xh, n4x);
        int n4w = DMODEL * DMODEL / 4;
        f2h_kernel<<<(n4w + 255) / 256, 256>>>((const float4*)Wq, (__half2*)(wh + 0 * WSZ), n4w);
        f2h_kernel<<<(n4w + 255) / 256, 256>>>((const float4*)Wk, (__half2*)(wh + 1 * WSZ), n4w);
        f2h_kernel<<<(n4w + 255) / 256, 256>>>((const float4*)Wv, (__half2*)(wh + 2 * WSZ), n4w);
    }

    const dim3 blk(256);
    const size_t sQK = (size_t)TSEQ * DMODEL;
    const size_t sS  = (size_t)TSEQ * TSEQ;

    // 1) Q = x Wq^T + bq, K = x Wk^T + bk   [16384,1024] half out
    {
        dim3 g(DMODEL / 128, BT_TOK / 128, 1);
        gemm_fp16<<<g, blk, SMEM_G>>>(xh, DMODEL, 0, wh + 0 * WSZ, DMODEL, 0,
                                      qh, DMODEL, 0, bq, 1, 1.0f, DMODEL, 1);
        gemm_fp16<<<g, blk, SMEM_G>>>(xh, DMODEL, 0, wh + 1 * WSZ, DMODEL, 0,
                                      kh, DMODEL, 0, bk, 1, 1.0f, DMODEL, 1);
    }
    // 1b) Vt = Wv x^T + bv(per-row)   [1024, 16384] half out
    {
        dim3 g(BT_TOK / 128, DMODEL / 128, 1);
        gemm_fp16<<<g, blk, SMEM_G>>>(wh + 2 * WSZ, DMODEL, 0, xh, DMODEL, 0,
                                      vth, BT_TOK, 0, bv, 2, 1.0f, DMODEL, 1);
    }
    // 2) S = Q K^T * scale per batch   [2048,2048] fp16 out (scores)
    {
        dim3 g(TSEQ / 128, TSEQ / 128, NBATCH);
        gemm_fp16<<<g, blk, SMEM_G>>>(qh, DMODEL, sQK, kh, DMODEL, sQK,
                                      ph, TSEQ, sS, nullptr, 0, SCALE, DMODEL, 1);
    }
    // 3) softmax rows in place (fp16 buffer)
    softmax2048<<<NBATCH * TSEQ, 256>>>(ph);

    // 4) O = P Vt^T per batch (fp32 out)
    {
        dim3 g(DMODEL / 128, TSEQ / 128, NBATCH);
        gemm_fp16<<<g, blk, SMEM_G>>>(ph, TSEQ, sS, vth, BT_TOK, (size_t)TSEQ,
                                      out, DMODEL, sQK, nullptr, 0, 1.0f, TSEQ, 0);
    }
}